// round 11
// baseline (speedup 1.0000x reference)
#include <cuda_runtime.h>
#include <math.h>

#define B_N 4096
#define F_N 2048
#define M_N 14
#define C_N 100
#define SMP 32
#define DPAD 129
#define PSTR 18      // pair-array stride in ull

typedef unsigned long long ull;

__device__ float g_Le[B_N * M_N];
__device__ float g_Ehi[C_N * 128];
__device__ float g_Elo[C_N * 128];
__device__ float g_Dinv[128 * 128];
__device__ float g_DinvL[128 * 128];
__device__ double g_acc;

__device__ __forceinline__ ull fma2(ull a, ull b, ull c) {
    ull d;
    asm("fma.rn.f32x2 %0, %1, %2, %3;" : "=l"(d) : "l"(a), "l"(b), "l"(c));
    return d;
}
__device__ __forceinline__ ull pk2(float v) {
    ull r;
    asm("mov.b64 %0, {%1, %1};" : "=l"(r) : "f"(v));
    return r;
}
__device__ __forceinline__ ull pkab(float a, float b) {
    ull r;
    asm("mov.b64 %0, {%1, %2};" : "=l"(r) : "f"(a), "f"(b));
    return r;
}

// ---------------------------------------------------------------------------
__global__ void k_ehilo(const float* __restrict__ beta0,
                        const float* __restrict__ beta) {
    if (blockIdx.x == 0 && threadIdx.x == 0) g_acc = 0.0;
    int c = blockIdx.x, t = threadIdx.x;
    if (t < 128) {
        float v = beta0[c];
#pragma unroll
        for (int j = 0; j < 7; j++)
            v += (((t >> (6 - j)) & 1) ? 1.f : -1.f) * beta[c * M_N + j];
        g_Ehi[c * 128 + t] = expf(v);
    } else if (t < 256) {
        int l = t - 128;
        float v = 0.f;
#pragma unroll
        for (int j = 0; j < 7; j++)
            v += (((l >> (6 - j)) & 1) ? 1.f : -1.f) * beta[c * M_N + 7 + j];
        g_Elo[c * 128 + l] = expf(v);
    }
}

// ---------------------------------------------------------------------------
__global__ void k_D() {
    int h = blockIdx.x, l = threadIdx.x;
    float d = 0.f;
#pragma unroll 4
    for (int c = 0; c < C_N; c++)
        d = fmaf(__ldg(&g_Ehi[c * 128 + h]), __ldg(&g_Elo[c * 128 + l]), d);
    float inv = 1.f / d;
    g_Dinv[h * 128 + l] = inv;
    g_DinvL[h * 128 + l] = logf(d) * inv;
}

// ---------------------------------------------------------------------------
// GEMM: 128 blocks x 256 thr; warp = 4 rows (2 row-pairs), 2-deep x prefetch.
// ---------------------------------------------------------------------------
__global__ void __launch_bounds__(256)
k_gemm(const float* __restrict__ x, const float* __restrict__ alpha,
       const float* __restrict__ alpha0) {
    int wid = threadIdx.x >> 5, lane = threadIdx.x & 31;
    int r0 = blockIdx.x * 32 + wid * 4;
    const float* xb = x + (size_t)r0 * F_N + lane * 4;

    ull acc[2][M_N];
#pragma unroll
    for (int p = 0; p < 2; p++)
#pragma unroll
        for (int j = 0; j < M_N; j++) acc[p][j] = 0ull;

    float4 xn0[4], xn1[4];
#pragma unroll
    for (int r = 0; r < 4; r++) {
        xn0[r] = *(const float4*)(xb + (size_t)r * F_N);
        xn1[r] = *(const float4*)(xb + (size_t)r * F_N + 128);
    }

#pragma unroll
    for (int ip = 0; ip < 8; ip++) {
        // even iter
        {
            int it = 2 * ip;
            ull xp[2][4];
#pragma unroll
            for (int p = 0; p < 2; p++) {
                xp[p][0] = pkab(xn0[2 * p].x, xn0[2 * p + 1].x);
                xp[p][1] = pkab(xn0[2 * p].y, xn0[2 * p + 1].y);
                xp[p][2] = pkab(xn0[2 * p].z, xn0[2 * p + 1].z);
                xp[p][3] = pkab(xn0[2 * p].w, xn0[2 * p + 1].w);
            }
            if (it + 2 < 16) {
#pragma unroll
                for (int r = 0; r < 4; r++)
                    xn0[r] = *(const float4*)(xb + (size_t)r * F_N + (it + 2) * 128);
            }
            int col = it * 128 + lane * 4;
#pragma unroll
            for (int j = 0; j < M_N; j++) {
                float4 av = __ldg((const float4*)&alpha[(size_t)j * F_N + col]);
                ull a0 = pk2(av.x), a1 = pk2(av.y), a2 = pk2(av.z), a3 = pk2(av.w);
#pragma unroll
                for (int p = 0; p < 2; p++) {
                    acc[p][j] = fma2(xp[p][0], a0, acc[p][j]);
                    acc[p][j] = fma2(xp[p][1], a1, acc[p][j]);
                    acc[p][j] = fma2(xp[p][2], a2, acc[p][j]);
                    acc[p][j] = fma2(xp[p][3], a3, acc[p][j]);
                }
            }
        }
        // odd iter
        {
            int it = 2 * ip + 1;
            ull xp[2][4];
#pragma unroll
            for (int p = 0; p < 2; p++) {
                xp[p][0] = pkab(xn1[2 * p].x, xn1[2 * p + 1].x);
                xp[p][1] = pkab(xn1[2 * p].y, xn1[2 * p + 1].y);
                xp[p][2] = pkab(xn1[2 * p].z, xn1[2 * p + 1].z);
                xp[p][3] = pkab(xn1[2 * p].w, xn1[2 * p + 1].w);
            }
            if (it + 2 < 16) {
#pragma unroll
                for (int r = 0; r < 4; r++)
                    xn1[r] = *(const float4*)(xb + (size_t)r * F_N + (it + 2) * 128);
            }
            int col = it * 128 + lane * 4;
#pragma unroll
            for (int j = 0; j < M_N; j++) {
                float4 av = __ldg((const float4*)&alpha[(size_t)j * F_N + col]);
                ull a0 = pk2(av.x), a1 = pk2(av.y), a2 = pk2(av.z), a3 = pk2(av.w);
#pragma unroll
                for (int p = 0; p < 2; p++) {
                    acc[p][j] = fma2(xp[p][0], a0, acc[p][j]);
                    acc[p][j] = fma2(xp[p][1], a1, acc[p][j]);
                    acc[p][j] = fma2(xp[p][2], a2, acc[p][j]);
                    acc[p][j] = fma2(xp[p][3], a3, acc[p][j]);
                }
            }
        }
    }

#pragma unroll
    for (int p = 0; p < 2; p++)
#pragma unroll
        for (int j = 0; j < M_N; j++) {
            float2 f = *(float2*)&acc[p][j];
#pragma unroll
            for (int m = 16; m >= 1; m >>= 1) {
                f.x += __shfl_xor_sync(0xffffffffu, f.x, m);
                f.y += __shfl_xor_sync(0xffffffffu, f.y, m);
            }
            if (lane == 0) {
                float a0v = alpha0[j];
                g_Le[(r0 + 2 * p) * M_N + j]     = a0v + f.x;
                g_Le[(r0 + 2 * p + 1) * M_N + j] = a0v + f.y;
            }
        }
}

// ---------------------------------------------------------------------------
// K_main: 128 blocks x 1024 thr, 32 samples. Sample-pair packed f32x2.
// Warps 0-15: V/R (+eii,denom fold).  Warps 16-31: U.
// ---------------------------------------------------------------------------
__global__ void __launch_bounds__(1024)
k_main(const int* __restrict__ y,
       const float* __restrict__ beta0,
       const float* __restrict__ beta) {
    extern __shared__ float sm[];
    float* sDi   = sm;                          // 128*129
    float* sDiL  = sDi + 128 * DPAD;            // 128*129
    ull*   sWloP = (ull*)(sDiL + 128 * DPAD);   // 128*PSTR ull
    ull*   sWhiP = sWloP + 128 * PSTR;          // 128*PSTR ull
    float* sWloS = (float*)(sWhiP + 128 * PSTR);// 32*128
    float* sV    = sWloS + SMP * 128;           // 32*128
    float* sU    = sV + SMP * 128;              // 32*128
    float* sq    = sU + SMP * 128;              // 32*14*2
    float* sle   = sq + SMP * M_N * 2;          // 32*14
    __shared__ int   sc[SMP];
    __shared__ float sEii[SMP * 4];
    __shared__ float sDen[SMP * 4];
    __shared__ float sspw[14];
    __shared__ float scontrib[SMP];

    int tid = threadIdx.x, lane = tid & 31;
    int b0s = blockIdx.x * SMP;

    if (tid < SMP) sc[tid] = y[b0s + tid];

    // Di/DiL staging (pad 129, scalar)
    for (int idx = tid; idx < 16384; idx += 1024) {
        int h = idx >> 7, l = idx & 127;
        sDi[h * DPAD + l]  = g_Dinv[idx];
        sDiL[h * DPAD + l] = g_DinvL[idx];
    }

    // sigmoid tables + EIV partials
    if (tid < SMP * M_N) {
        int s = tid / M_N, j = tid % M_N;
        float le = g_Le[(b0s + s) * M_N + j];
        sle[s * M_N + j] = le;
        float e = expf(-fabsf(le));
        float iv = 1.f / (1.f + e);
        sq[(s * M_N + j) * 2 + 0] = (le >= 0.f) ? e * iv : iv;
        sq[(s * M_N + j) * 2 + 1] = (le >= 0.f) ? iv : e * iv;
        float sp = fmaxf(le, 0.f) + log1pf(e);
#pragma unroll
        for (int m = 16; m >= 1; m >>= 1)
            sp += __shfl_xor_sync(0xffffffffu, sp, m);
        if (lane == 0) sspw[tid >> 5] = sp;
    }
    __syncthreads();

    // build whi/wlo pair arrays (+ wlo scalar copy for finalize)
    for (int v = tid; v < 16 * 128; v += 1024) {
        int p = v >> 7, idx = v & 127;
        int c0 = sc[2 * p], c1 = sc[2 * p + 1];
        float ph0 = __ldg(&g_Ehi[c0 * 128 + idx]);
        float ph1 = __ldg(&g_Ehi[c1 * 128 + idx]);
        float pl0 = __ldg(&g_Elo[c0 * 128 + idx]);
        float pl1 = __ldg(&g_Elo[c1 * 128 + idx]);
#pragma unroll
        for (int j = 0; j < 7; j++) {
            int bit = ((idx >> (6 - j)) & 1);
            ph0 *= sq[((2 * p) * M_N + j) * 2 + bit];
            ph1 *= sq[((2 * p + 1) * M_N + j) * 2 + bit];
            pl0 *= sq[((2 * p) * M_N + 7 + j) * 2 + bit];
            pl1 *= sq[((2 * p + 1) * M_N + 7 + j) * 2 + bit];
        }
        sWhiP[idx * PSTR + p] = pkab(ph0, ph1);
        sWloP[idx * PSTR + p] = pkab(pl0, pl1);
        sWloS[(2 * p) * 128 + idx] = pl0;
        sWloS[(2 * p + 1) * 128 + idx] = pl1;
    }
    __syncthreads();

    if (tid < 512) {
        // ---- V/R pass: thread (h, sg) -> 8 samples (4 pairs) ----
        int h = tid & 127, sg = (tid >> 7) & 3;
        int sb = sg * 8, hgrp = (tid >> 5) & 3;
        const float* rowD  = sDi + h * DPAD;
        const float* rowDL = sDiL + h * DPAD;
        const ull* pb = sWloP + sg * 4;
        ull aV[4], aR[4];
#pragma unroll
        for (int p = 0; p < 4; p++) { aV[p] = 0ull; aR[p] = 0ull; }
#pragma unroll 4
        for (int l = 0; l < 128; l++) {
            ull d2 = pk2(rowD[l]);
            ull e2 = pk2(rowDL[l]);
            ulonglong2 w01 = *(const ulonglong2*)(pb + l * PSTR);
            ulonglong2 w23 = *(const ulonglong2*)(pb + l * PSTR + 2);
            aV[0] = fma2(d2, w01.x, aV[0]);
            aV[1] = fma2(d2, w01.y, aV[1]);
            aV[2] = fma2(d2, w23.x, aV[2]);
            aV[3] = fma2(d2, w23.y, aV[3]);
            aR[0] = fma2(e2, w01.x, aR[0]);
            aR[1] = fma2(e2, w01.y, aR[1]);
            aR[2] = fma2(e2, w23.x, aR[2]);
            aR[3] = fma2(e2, w23.y, aR[3]);
        }
#pragma unroll
        for (int p = 0; p < 4; p++) {
            ull wp = sWhiP[h * PSTR + sg * 4 + p];
            float2 w = *(float2*)&wp;
            float2 Vv = *(float2*)&aV[p];
            float2 Rv = *(float2*)&aR[p];
            sV[(sb + 2 * p) * 128 + h]     = Vv.x;
            sV[(sb + 2 * p + 1) * 128 + h] = Vv.y;
            float ep0 = w.x * Rv.x, ep1 = w.y * Rv.y;
            float dn0 = w.x * Vv.x, dn1 = w.y * Vv.y;
#pragma unroll
            for (int m = 16; m >= 1; m >>= 1) {
                ep0 += __shfl_xor_sync(0xffffffffu, ep0, m);
                ep1 += __shfl_xor_sync(0xffffffffu, ep1, m);
                dn0 += __shfl_xor_sync(0xffffffffu, dn0, m);
                dn1 += __shfl_xor_sync(0xffffffffu, dn1, m);
            }
            if (lane == 0) {
                sEii[(sb + 2 * p) * 4 + hgrp]     = ep0;
                sEii[(sb + 2 * p + 1) * 4 + hgrp] = ep1;
                sDen[(sb + 2 * p) * 4 + hgrp]     = dn0;
                sDen[(sb + 2 * p + 1) * 4 + hgrp] = dn1;
            }
        }
    } else {
        // ---- U pass: thread (l, sg) -> 8 samples (4 pairs) ----
        int l = tid & 127, sg = (tid >> 7) & 3;
        int sb = sg * 8;
        const ull* pb = sWhiP + sg * 4;
        ull aU[4];
#pragma unroll
        for (int p = 0; p < 4; p++) aU[p] = 0ull;
#pragma unroll 4
        for (int h = 0; h < 128; h++) {
            ull d2 = pk2(sDi[h * DPAD + l]);
            ulonglong2 w01 = *(const ulonglong2*)(pb + h * PSTR);
            ulonglong2 w23 = *(const ulonglong2*)(pb + h * PSTR + 2);
            aU[0] = fma2(d2, w01.x, aU[0]);
            aU[1] = fma2(d2, w01.y, aU[1]);
            aU[2] = fma2(d2, w23.x, aU[2]);
            aU[3] = fma2(d2, w23.y, aU[3]);
        }
#pragma unroll
        for (int p = 0; p < 4; p++) {
            float2 u = *(float2*)&aU[p];
            sU[(sb + 2 * p) * 128 + l]     = u.x;
            sU[(sb + 2 * p + 1) * 128 + l] = u.y;
        }
    }
    __syncthreads();

    // ---- finalize: warp w -> sample w ----
    int w = tid >> 5;
    {
        int c = sc[w];
        float nh[7] = {0, 0, 0, 0, 0, 0, 0};
        float nl[7] = {0, 0, 0, 0, 0, 0, 0};
        float4 V4   = *(const float4*)&sV[w * 128 + lane * 4];
        float4 U4   = *(const float4*)&sU[w * 128 + lane * 4];
        float4 wlo4 = *(const float4*)&sWloS[w * 128 + lane * 4];
        const float* VA = (const float*)&V4;
        const float* UA = (const float*)&U4;
        const float* wloA = (const float*)&wlo4;
#pragma unroll
        for (int q = 0; q < 4; q++) {
            int h = lane * 4 + q;
            float whv = __ldg(&g_Ehi[c * 128 + h]);
#pragma unroll
            for (int j = 0; j < 7; j++)
                whv *= sq[(w * M_N + j) * 2 + ((h >> (6 - j)) & 1)];
            float wv = whv * VA[q];
            float wu = wloA[q] * UA[q];
#pragma unroll
            for (int j = 0; j < 7; j++) {
                float bit = (float)((h >> (6 - j)) & 1);
                nh[j] = fmaf(bit, wv, nh[j]);
                nl[j] = fmaf(bit, wu, nl[j]);
            }
        }
#pragma unroll
        for (int m = 16; m >= 1; m >>= 1) {
#pragma unroll
            for (int j = 0; j < 7; j++) {
                nh[j] += __shfl_xor_sync(0xffffffffu, nh[j], m);
                nl[j] += __shfl_xor_sync(0xffffffffu, nl[j], m);
            }
        }
        if (lane == 0) {
            float den = sDen[w * 4 + 0] + sDen[w * 4 + 1]
                      + sDen[w * 4 + 2] + sDen[w * 4 + 3];
            float eii = sEii[w * 4 + 0] + sEii[w * 4 + 1]
                      + sEii[w * 4 + 2] + sEii[w * 4 + 3];
            float inv = 1.f / den;
            float contrib = beta0[c] - eii * inv;
#pragma unroll
            for (int j = 0; j < 7; j++) {
                float Ez = nh[j] * inv;
                contrib += (2.f * Ez - 1.f) * beta[c * M_N + j]
                         + Ez * sle[w * M_N + j];
            }
#pragma unroll
            for (int j = 7; j < 14; j++) {
                float Ez = nl[j - 7] * inv;
                contrib += (2.f * Ez - 1.f) * beta[c * M_N + j]
                         + Ez * sle[w * M_N + j];
            }
            scontrib[w] = contrib;
        }
    }
    __syncthreads();
    if (tid == 0) {
        float t = 0.f;
#pragma unroll
        for (int s = 0; s < SMP; s++) t += scontrib[s];
#pragma unroll
        for (int q = 0; q < 14; q++) t -= sspw[q];   // -EIV
        atomicAdd(&g_acc, (double)t);
    }
}

__global__ void k_fin(float* out) { out[0] = (float)g_acc; }

extern "C" void kernel_launch(void* const* d_in, const int* in_sizes, int n_in,
                              void* d_out, int out_size) {
    const float* x   = (const float*)d_in[0];
    const int*   y   = (const int*)d_in[1];
    const float* a0  = (const float*)d_in[2];
    const float* al  = (const float*)d_in[3];
    const float* b0  = (const float*)d_in[4];
    const float* be  = (const float*)d_in[5];
    float* out = (float*)d_out;

    const int SMEM4 = (2 * 128 * DPAD + 2 * 128 * PSTR * 2 + 3 * SMP * 128
                       + SMP * M_N * 2 + SMP * M_N) * 4;   // ~223.5KB
    cudaFuncSetAttribute(k_main, cudaFuncAttributeMaxDynamicSharedMemorySize, SMEM4);

    k_ehilo<<<C_N, 256>>>(b0, be);
    k_D<<<128, 128>>>();
    k_gemm<<<B_N / 32, 256>>>(x, al, a0);
    k_main<<<B_N / SMP, 1024, SMEM4>>>(y, b0, be);
    k_fin<<<1, 1>>>(out);
}

// round 13
// speedup vs baseline: 1.2096x; 1.2096x over previous
#include <cuda_runtime.h>
#include <math.h>

#define B_N 4096
#define F_N 2048
#define M_N 14
#define C_N 100
#define SMP 32
#define DPAD 129
#define PSTR 18      // pair-array stride in ull

typedef unsigned long long ull;

__device__ float g_Le[B_N * M_N];
__device__ float g_Ehi[C_N * 128];
__device__ float g_Elo[C_N * 128];
__device__ float g_Dinv[128 * 128];
__device__ float g_DinvL[128 * 128];
__device__ double g_acc;
__device__ unsigned g_done;

__device__ __forceinline__ ull fma2(ull a, ull b, ull c) {
    ull d;
    asm("fma.rn.f32x2 %0, %1, %2, %3;" : "=l"(d) : "l"(a), "l"(b), "l"(c));
    return d;
}
__device__ __forceinline__ ull pk2(float v) {
    ull r;
    asm("mov.b64 %0, {%1, %1};" : "=l"(r) : "f"(v));
    return r;
}
__device__ __forceinline__ ull pkab(float a, float b) {
    ull r;
    asm("mov.b64 %0, {%1, %2};" : "=l"(r) : "f"(a), "f"(b));
    return r;
}

// ---------------------------------------------------------------------------
__global__ void k_ehilo(const float* __restrict__ beta0,
                        const float* __restrict__ beta) {
    if (blockIdx.x == 0 && threadIdx.x == 0) { g_acc = 0.0; g_done = 0u; }
    int c = blockIdx.x, t = threadIdx.x;
    if (t < 128) {
        float v = beta0[c];
#pragma unroll
        for (int j = 0; j < 7; j++)
            v += (((t >> (6 - j)) & 1) ? 1.f : -1.f) * beta[c * M_N + j];
        g_Ehi[c * 128 + t] = expf(v);
    } else if (t < 256) {
        int l = t - 128;
        float v = 0.f;
#pragma unroll
        for (int j = 0; j < 7; j++)
            v += (((l >> (6 - j)) & 1) ? 1.f : -1.f) * beta[c * M_N + 7 + j];
        g_Elo[c * 128 + l] = expf(v);
    }
}

// ---------------------------------------------------------------------------
// D: grid 128 (h), 512 thr; c-range split 4-way for MLP; smem combine.
// ---------------------------------------------------------------------------
__global__ void __launch_bounds__(512)
k_D() {
    __shared__ float sp[4][128];
    int t = threadIdx.x, l = t & 127, qt = t >> 7;
    int h = blockIdx.x;
    float part = 0.f;
    int c0 = qt * 25;
#pragma unroll
    for (int c = 0; c < 25; c++)
        part = fmaf(__ldg(&g_Ehi[(c0 + c) * 128 + h]),
                    __ldg(&g_Elo[(c0 + c) * 128 + l]), part);
    sp[qt][l] = part;
    __syncthreads();
    if (t < 128) {
        float d = sp[0][l] + sp[1][l] + sp[2][l] + sp[3][l];
        float inv = 1.f / d;
        g_Dinv[h * 128 + l] = inv;
        g_DinvL[h * 128 + l] = logf(d) * inv;
    }
}

// ---------------------------------------------------------------------------
// GEMM: 128 blocks x 128 thr; warp = 8 rows (4 row-pairs) packed f32x2.
// x streamed (__ldcs), alpha via L1 (__ldg).
// ---------------------------------------------------------------------------
__global__ void __launch_bounds__(128)
k_gemm(const float* __restrict__ x, const float* __restrict__ alpha,
       const float* __restrict__ alpha0) {
    int wid = threadIdx.x >> 5, lane = threadIdx.x & 31;
    int r0 = blockIdx.x * 32 + wid * 8;

    ull acc[4][M_N];
#pragma unroll
    for (int p = 0; p < 4; p++)
#pragma unroll
        for (int j = 0; j < M_N; j++) acc[p][j] = 0ull;

    float4 xn[8];
#pragma unroll
    for (int r = 0; r < 8; r++)
        xn[r] = __ldcs((const float4*)&x[(size_t)(r0 + r) * F_N + lane * 4]);

    for (int it = 0; it < 16; it++) {
        int col = it * 128 + lane * 4;
        ull xp[4][4];
#pragma unroll
        for (int p = 0; p < 4; p++) {
            xp[p][0] = pkab(xn[2 * p].x, xn[2 * p + 1].x);
            xp[p][1] = pkab(xn[2 * p].y, xn[2 * p + 1].y);
            xp[p][2] = pkab(xn[2 * p].z, xn[2 * p + 1].z);
            xp[p][3] = pkab(xn[2 * p].w, xn[2 * p + 1].w);
        }
        if (it < 15) {
#pragma unroll
            for (int r = 0; r < 8; r++)
                xn[r] = __ldcs((const float4*)&x[(size_t)(r0 + r) * F_N + col + 128]);
        }
#pragma unroll
        for (int j = 0; j < M_N; j++) {
            float4 av = __ldg((const float4*)&alpha[(size_t)j * F_N + col]);
            ull a0 = pk2(av.x), a1 = pk2(av.y), a2 = pk2(av.z), a3 = pk2(av.w);
#pragma unroll
            for (int p = 0; p < 4; p++) {
                acc[p][j] = fma2(xp[p][0], a0, acc[p][j]);
                acc[p][j] = fma2(xp[p][1], a1, acc[p][j]);
                acc[p][j] = fma2(xp[p][2], a2, acc[p][j]);
                acc[p][j] = fma2(xp[p][3], a3, acc[p][j]);
            }
        }
    }

#pragma unroll
    for (int p = 0; p < 4; p++)
#pragma unroll
        for (int j = 0; j < M_N; j++) {
            float2 f = *(float2*)&acc[p][j];
#pragma unroll
            for (int m = 16; m >= 1; m >>= 1) {
                f.x += __shfl_xor_sync(0xffffffffu, f.x, m);
                f.y += __shfl_xor_sync(0xffffffffu, f.y, m);
            }
            if (lane == 0) {
                float a0v = alpha0[j];
                g_Le[(r0 + 2 * p) * M_N + j]     = a0v + f.x;
                g_Le[(r0 + 2 * p + 1) * M_N + j] = a0v + f.y;
            }
        }
}

// ---------------------------------------------------------------------------
// K_main: 128 blocks x 1024 thr, 32 samples. Sample-pair packed f32x2.
// Warps 0-15: V,R (stores only, no shuffles). Warps 16-31: U.
// den/eii folded into finalize. Last block writes the output.
// ---------------------------------------------------------------------------
__global__ void __launch_bounds__(1024)
k_main(const int* __restrict__ y,
       const float* __restrict__ beta0,
       const float* __restrict__ beta,
       float* __restrict__ out) {
    extern __shared__ float sm[];
    float* sDi   = sm;                          // 128*129
    float* sDiL  = sDi + 128 * DPAD;            // 128*129
    ull*   sWloP = (ull*)(sDiL + 128 * DPAD);   // 128*PSTR ull
    ull*   sWhiP = sWloP + 128 * PSTR;          // 128*PSTR ull
    float* sV    = (float*)(sWhiP + 128 * PSTR);// 32*128
    float* sR    = sV + SMP * 128;              // 32*128
    float* sU    = sR + SMP * 128;              // 32*128
    float* sq    = sU + SMP * 128;              // 32*14*2
    float* sle   = sq + SMP * M_N * 2;          // 32*14
    __shared__ int   sc[SMP];
    __shared__ float sspw[14];
    __shared__ float scontrib[SMP];

    int tid = threadIdx.x, lane = tid & 31;
    int b0s = blockIdx.x * SMP;

    if (tid < SMP) sc[tid] = y[b0s + tid];

    // Di/DiL staging: float4 loads, scalar stores into pad-129 layout
    for (int i = tid; i < 4096; i += 1024) {
        float4 a = ((const float4*)g_Dinv)[i];
        float4 b = ((const float4*)g_DinvL)[i];
        int h = i >> 5, q = i & 31;
        float* p1 = sDi + h * DPAD + q * 4;
        float* p2 = sDiL + h * DPAD + q * 4;
        p1[0] = a.x; p1[1] = a.y; p1[2] = a.z; p1[3] = a.w;
        p2[0] = b.x; p2[1] = b.y; p2[2] = b.z; p2[3] = b.w;
    }

    // sigmoid tables + EIV partials
    if (tid < SMP * M_N) {
        int s = tid / M_N, j = tid % M_N;
        float le = g_Le[(b0s + s) * M_N + j];
        sle[s * M_N + j] = le;
        float e = expf(-fabsf(le));
        float iv = 1.f / (1.f + e);
        sq[(s * M_N + j) * 2 + 0] = (le >= 0.f) ? e * iv : iv;
        sq[(s * M_N + j) * 2 + 1] = (le >= 0.f) ? iv : e * iv;
        float sp = fmaxf(le, 0.f) + log1pf(e);
#pragma unroll
        for (int m = 16; m >= 1; m >>= 1)
            sp += __shfl_xor_sync(0xffffffffu, sp, m);
        if (lane == 0) sspw[tid >> 5] = sp;
    }
    __syncthreads();

    // build whi/wlo pair arrays
    for (int v = tid; v < 16 * 128; v += 1024) {
        int p = v >> 7, idx = v & 127;
        int c0 = sc[2 * p], c1 = sc[2 * p + 1];
        float ph0 = __ldg(&g_Ehi[c0 * 128 + idx]);
        float ph1 = __ldg(&g_Ehi[c1 * 128 + idx]);
        float pl0 = __ldg(&g_Elo[c0 * 128 + idx]);
        float pl1 = __ldg(&g_Elo[c1 * 128 + idx]);
#pragma unroll
        for (int j = 0; j < 7; j++) {
            int bit = ((idx >> (6 - j)) & 1);
            ph0 *= sq[((2 * p) * M_N + j) * 2 + bit];
            ph1 *= sq[((2 * p + 1) * M_N + j) * 2 + bit];
            pl0 *= sq[((2 * p) * M_N + 7 + j) * 2 + bit];
            pl1 *= sq[((2 * p + 1) * M_N + 7 + j) * 2 + bit];
        }
        sWhiP[idx * PSTR + p] = pkab(ph0, ph1);
        sWloP[idx * PSTR + p] = pkab(pl0, pl1);
    }
    __syncthreads();

    if (tid < 512) {
        // ---- V/R pass: thread (h, sg) -> 8 samples, stores only ----
        int h = tid & 127, sg = (tid >> 7) & 3;
        int sb = sg * 8;
        const float* rowD  = sDi + h * DPAD;
        const float* rowDL = sDiL + h * DPAD;
        const ull* pb = sWloP + sg * 4;
        ull aV[4], aR[4];
#pragma unroll
        for (int p = 0; p < 4; p++) { aV[p] = 0ull; aR[p] = 0ull; }
#pragma unroll 4
        for (int l = 0; l < 128; l++) {
            ull d2 = pk2(rowD[l]);
            ull e2 = pk2(rowDL[l]);
            ulonglong2 w01 = *(const ulonglong2*)(pb + l * PSTR);
            ulonglong2 w23 = *(const ulonglong2*)(pb + l * PSTR + 2);
            aV[0] = fma2(d2, w01.x, aV[0]);
            aV[1] = fma2(d2, w01.y, aV[1]);
            aV[2] = fma2(d2, w23.x, aV[2]);
            aV[3] = fma2(d2, w23.y, aV[3]);
            aR[0] = fma2(e2, w01.x, aR[0]);
            aR[1] = fma2(e2, w01.y, aR[1]);
            aR[2] = fma2(e2, w23.x, aR[2]);
            aR[3] = fma2(e2, w23.y, aR[3]);
        }
#pragma unroll
        for (int p = 0; p < 4; p++) {
            float2 Vv = *(float2*)&aV[p];
            float2 Rv = *(float2*)&aR[p];
            sV[(sb + 2 * p) * 128 + h]     = Vv.x;
            sV[(sb + 2 * p + 1) * 128 + h] = Vv.y;
            sR[(sb + 2 * p) * 128 + h]     = Rv.x;
            sR[(sb + 2 * p + 1) * 128 + h] = Rv.y;
        }
    } else {
        // ---- U pass: thread (l, sg) -> 8 samples ----
        int l = tid & 127, sg = (tid >> 7) & 3;
        int sb = sg * 8;
        const ull* pb = sWhiP + sg * 4;
        ull aU[4];
#pragma unroll
        for (int p = 0; p < 4; p++) aU[p] = 0ull;
#pragma unroll 4
        for (int h = 0; h < 128; h++) {
            ull d2 = pk2(sDi[h * DPAD + l]);
            ulonglong2 w01 = *(const ulonglong2*)(pb + h * PSTR);
            ulonglong2 w23 = *(const ulonglong2*)(pb + h * PSTR + 2);
            aU[0] = fma2(d2, w01.x, aU[0]);
            aU[1] = fma2(d2, w01.y, aU[1]);
            aU[2] = fma2(d2, w23.x, aU[2]);
            aU[3] = fma2(d2, w23.y, aU[3]);
        }
#pragma unroll
        for (int p = 0; p < 4; p++) {
            float2 u = *(float2*)&aU[p];
            sU[(sb + 2 * p) * 128 + l]     = u.x;
            sU[(sb + 2 * p + 1) * 128 + l] = u.y;
        }
    }
    __syncthreads();

    // ---- finalize: warp w -> sample w (den/eii computed here) ----
    int w = tid >> 5;
    {
        int c = sc[w];
        int wp_idx = w >> 1, wp_sel = w & 1;
        float dacc = 0.f, eacc = 0.f;
        float nh[7] = {0, 0, 0, 0, 0, 0, 0};
        float nl[7] = {0, 0, 0, 0, 0, 0, 0};
        float4 V4 = *(const float4*)&sV[w * 128 + lane * 4];
        float4 R4 = *(const float4*)&sR[w * 128 + lane * 4];
        float4 U4 = *(const float4*)&sU[w * 128 + lane * 4];
        const float* VA = (const float*)&V4;
        const float* RA = (const float*)&R4;
        const float* UA = (const float*)&U4;
#pragma unroll
        for (int q = 0; q < 4; q++) {
            int h = lane * 4 + q;
            float whv = __ldg(&g_Ehi[c * 128 + h]);
#pragma unroll
            for (int j = 0; j < 7; j++)
                whv *= sq[(w * M_N + j) * 2 + ((h >> (6 - j)) & 1)];
            float2 wp = *(float2*)&sWloP[h * PSTR + wp_idx];
            float wlov = wp_sel ? wp.y : wp.x;
            float wv = whv * VA[q];
            dacc += wv;
            eacc = fmaf(whv, RA[q], eacc);
            float wu = wlov * UA[q];
#pragma unroll
            for (int j = 0; j < 7; j++) {
                float bit = (float)((h >> (6 - j)) & 1);
                nh[j] = fmaf(bit, wv, nh[j]);
                nl[j] = fmaf(bit, wu, nl[j]);
            }
        }
#pragma unroll
        for (int m = 16; m >= 1; m >>= 1) {
            dacc += __shfl_xor_sync(0xffffffffu, dacc, m);
            eacc += __shfl_xor_sync(0xffffffffu, eacc, m);
#pragma unroll
            for (int j = 0; j < 7; j++) {
                nh[j] += __shfl_xor_sync(0xffffffffu, nh[j], m);
                nl[j] += __shfl_xor_sync(0xffffffffu, nl[j], m);
            }
        }
        if (lane == 0) {
            float inv = 1.f / dacc;
            float contrib = beta0[c] - eacc * inv;
#pragma unroll
            for (int j = 0; j < 7; j++) {
                float Ez = nh[j] * inv;
                contrib += (2.f * Ez - 1.f) * beta[c * M_N + j]
                         + Ez * sle[w * M_N + j];
            }
#pragma unroll
            for (int j = 7; j < 14; j++) {
                float Ez = nl[j - 7] * inv;
                contrib += (2.f * Ez - 1.f) * beta[c * M_N + j]
                         + Ez * sle[w * M_N + j];
            }
            scontrib[w] = contrib;
        }
    }
    __syncthreads();
    if (tid == 0) {
        float t = 0.f;
#pragma unroll
        for (int s = 0; s < SMP; s++) t += scontrib[s];
#pragma unroll
        for (int q = 0; q < 14; q++) t -= sspw[q];   // -EIV
        atomicAdd(&g_acc, (double)t);
        __threadfence();
        unsigned fin = atomicAdd(&g_done, 1u);
        if (fin == gridDim.x - 1) {
            double total = atomicAdd(&g_acc, 0.0);   // coherent read
            out[0] = (float)total;
            g_done = 0;                              // reset for next replay
        }
    }
}

extern "C" void kernel_launch(void* const* d_in, const int* in_sizes, int n_in,
                              void* d_out, int out_size) {
    const float* x   = (const float*)d_in[0];
    const int*   y   = (const int*)d_in[1];
    const float* a0  = (const float*)d_in[2];
    const float* al  = (const float*)d_in[3];
    const float* b0  = (const float*)d_in[4];
    const float* be  = (const float*)d_in[5];
    float* out = (float*)d_out;

    const int SMEM4 = (2 * 128 * DPAD + 2 * 128 * PSTR * 2 + 3 * SMP * 128
                       + SMP * M_N * 2 + SMP * M_N) * 4;   // ~223.5KB
    cudaFuncSetAttribute(k_main, cudaFuncAttributeMaxDynamicSharedMemorySize, SMEM4);

    k_ehilo<<<C_N, 256>>>(b0, be);
    k_D<<<128, 512>>>();
    k_gemm<<<B_N / 32, 128>>>(x, al, a0);
    k_main<<<B_N / SMP, 1024, SMEM4>>>(y, b0, be, out);
}